// round 3
// baseline (speedup 1.0000x reference)
#include <cuda_runtime.h>
#include <cuda_fp16.h>
#include <math.h>

#define B_ 64
#define N_ 4096
#define V_ 21
#define S_ 50
#define E_ 64
#define H_ 128
#define THREADS 512
#define NCTAS 148

#define PADH 136        // halves per padded smem row (272B, 16B aligned, conflict-free ldmatrix)
#define PADH2 68

// ---------------- static device scratch ----------------
__device__ __half g_U16[512*H_];   // rows 0-127 Ui, 128-255 Uo, 256-383 Uu, 384-511 Uf (row r = U[r][:])
__device__ float  g_tai[S_*H_], g_tao[S_*H_], g_tau[S_*H_], g_taf[S_*H_];
__device__ __half g_h016[V_*H_];
__device__ float  g_c0[V_*H_];
__device__ __half g_HA[B_*2048*H_];
__device__ __half g_HB[B_*1024*H_];
__device__ float  g_CA[B_*2048*H_];
__device__ float  g_CB[B_*1024*H_];
__device__ float  g_hroot[B_*H_];
__device__ unsigned g_bar;

__device__ __forceinline__ float sigmf_(float x){
  return __fdividef(1.f, 1.f + __expf(-x));
}
__device__ __forceinline__ float tanhf_(float x){
  return 2.f*__fdividef(1.f, 1.f + __expf(-2.f*x)) - 1.f;
}

// ---------------- prep: leaf/symbol tables ----------------
__global__ void tables_kernel(const float* __restrict__ emb, const float* __restrict__ sym_emb,
                              const float* __restrict__ Wp, const float* __restrict__ bp,
                              const float* __restrict__ Wi, const float* __restrict__ bi,
                              const float* __restrict__ Wf, const float* __restrict__ bf,
                              const float* __restrict__ Wo, const float* __restrict__ bo,
                              const float* __restrict__ Wu, const float* __restrict__ bu){
  __shared__ float se[E_];
  __shared__ float sx[H_];
  int h   = threadIdx.x;
  int idx = blockIdx.x;
  if (idx == 0 && h == 0) g_bar = 0u;
  if (idx < V_) {
    int v = idx;
    if (h < E_) se[h] = emb[v*E_ + h];
    __syncthreads();
    float x = bp[h];
    #pragma unroll 8
    for (int e = 0; e < E_; e++) x += se[e]*Wp[h*E_ + e];
    sx[h] = x;
    __syncthreads();
    float ai_ = bi[h], ao_ = bo[h], au_ = bu[h];
    #pragma unroll 8
    for (int k = 0; k < H_; k++){
      float xv = sx[k];
      ai_ += xv*Wi[h*H_+k];
      ao_ += xv*Wo[h*H_+k];
      au_ += xv*Wu[h*H_+k];
    }
    float gi = 1.f/(1.f+expf(-ai_)), go = 1.f/(1.f+expf(-ao_)), gu = tanhf(au_);
    float c = gi*gu;
    g_c0[v*H_+h] = c;
    g_h016[v*H_+h] = __float2half(go*tanhf(c));
  } else {
    int s = idx - V_;
    if (h < E_) se[h] = sym_emb[s*E_ + h];
    __syncthreads();
    float x = bp[h];
    #pragma unroll 8
    for (int e = 0; e < E_; e++) x += se[e]*Wp[h*E_ + e];
    sx[h] = x;
    __syncthreads();
    float ai_ = bi[h], ao_ = bo[h], au_ = bu[h], af_ = bf[h];
    #pragma unroll 8
    for (int k = 0; k < H_; k++){
      float xv = sx[k];
      ai_ += xv*Wi[h*H_+k];
      ao_ += xv*Wo[h*H_+k];
      au_ += xv*Wu[h*H_+k];
      af_ += xv*Wf[h*H_+k];
    }
    g_tai[s*H_+h] = ai_;
    g_tao[s*H_+h] = ao_;
    g_tau[s*H_+h] = au_;
    g_taf[s*H_+h] = af_;
  }
}

// ---------------- prep: fp16 U-concat ----------------
__global__ void prepU_kernel(const float* __restrict__ Ui, const float* __restrict__ Uo,
                             const float* __restrict__ Uu, const float* __restrict__ Uf){
  int idx = blockIdx.x*blockDim.x + threadIdx.x;     // 0..65535
  int r = idx >> 7, k = idx & 127;
  float v;
  if      (r < 128) v = Ui[r*H_ + k];
  else if (r < 256) v = Uo[(r-128)*H_ + k];
  else if (r < 384) v = Uu[(r-256)*H_ + k];
  else              v = Uf[(r-384)*H_ + k];
  g_U16[idx] = __float2half(v);
}

// ---------------- mma helpers ----------------
__device__ __forceinline__ unsigned saddr(const void* p){
  return (unsigned)__cvta_generic_to_shared(p);
}
__device__ __forceinline__ void ldsm4(unsigned addr, unsigned &r0, unsigned &r1, unsigned &r2, unsigned &r3){
  asm volatile("ldmatrix.sync.aligned.m8n8.x4.shared.b16 {%0,%1,%2,%3}, [%4];"
    : "=r"(r0),"=r"(r1),"=r"(r2),"=r"(r3) : "r"(addr));
}
__device__ __forceinline__ void mma16816(float d[4], const unsigned a[4], unsigned b0, unsigned b1){
  asm volatile("mma.sync.aligned.m16n8k16.row.col.f32.f16.f16.f32 "
    "{%0,%1,%2,%3}, {%4,%5,%6,%7}, {%8,%9}, {%0,%1,%2,%3};"
    : "+f"(d[0]),"+f"(d[1]),"+f"(d[2]),"+f"(d[3])
    : "r"(a[0]),"r"(a[1]),"r"(a[2]),"r"(a[3]), "r"(b0),"r"(b1));
}

// ---------------- persistent tree kernel ----------------
// grid = 148 CTAs, 512 threads (16 warps: wm=wid/4 rows, wn=wid%4 cols)
// per tile: 64 nodes. GEMM1: ht[64x128] @ Uiou[384x128]^T. GEMM2: [hl;hr][128x128] @ Uf^T.
extern __shared__ __half smem_[];
__global__ __launch_bounds__(THREADS, 1) void tree_kernel(
  const int* __restrict__ tokens, const int* __restrict__ symbols,
  const float* __restrict__ Wout, const float* __restrict__ bout,
  float* __restrict__ out)
{
  __half* sB  = smem_;                 // 512 x PADH
  __half* sHT = sB + 512*PADH;         // 64 x PADH
  __half* sLR = sHT + 64*PADH;         // 128 x PADH (rows 0-63 hl, 64-127 hr)
  int* sSym   = (int*)(sLR + 128*PADH);
  int* sIdx0  = sSym + 64;
  int* sIdx1  = sIdx0 + 64;

  const int tid  = threadIdx.x;
  const int lane = tid & 31, wid = tid >> 5;
  const int wm   = wid >> 2, wn = wid & 3;

  // stage U (shared across all levels) once
  {
    const __half2* src = (const __half2*)g_U16;
    __half2* dst = (__half2*)sB;
    for (int idx = tid; idx < 512*64; idx += THREADS){
      int r = idx >> 6, k2 = idx & 63;
      dst[r*PADH2 + k2] = src[idx];
    }
  }
  __syncthreads();

  int m = 2048, off = 0;
  for (int lvl = 0; lvl < 12; lvl++){
    const __half* Hsrc; const float* Csrc;
    __half* Hdst; float* Cdst;
    if (lvl == 0)      { Hsrc = g_h016; Csrc = g_c0; }
    else if (lvl & 1)  { Hsrc = g_HA;   Csrc = g_CA; }
    else               { Hsrc = g_HB;   Csrc = g_CB; }
    if (lvl & 1) { Hdst = g_HB; Cdst = g_CB; } else { Hdst = g_HA; Cdst = g_CA; }

    const int tiles = (B_ * m) >> 6;
    const int logm  = 31 - __clz(m);

    for (int t = blockIdx.x; t < tiles; t += NCTAS){
      const int node0 = t << 6;
      // index phase
      if (tid < 64){
        int n_g = node0 + tid;
        int b = n_g >> logm, j = n_g & (m-1);
        sSym[tid] = symbols[b*(N_-1) + off + j];
        if (lvl == 0){
          sIdx0[tid] = tokens[b*N_ + 2*j];
          sIdx1[tid] = tokens[b*N_ + 2*j + 1];
        } else {
          sIdx0[tid] = 2*n_g;
          sIdx1[tid] = 2*n_g + 1;
        }
      }
      __syncthreads();
      // A staging: hl/hr rows + ht = hl+hr
      {
        const __half2* hs = (const __half2*)Hsrc;
        __half2* ht2 = (__half2*)sHT;
        __half2* lr2 = (__half2*)sLR;
        for (int idx = tid; idx < 64*64; idx += THREADS){
          int r = idx >> 6, k2 = idx & 63;
          __half2 a  = hs[sIdx0[r]*64 + k2];
          __half2 b2 = hs[sIdx1[r]*64 + k2];
          lr2[r*PADH2 + k2]        = a;
          lr2[(64 + r)*PADH2 + k2] = b2;
          ht2[r*PADH2 + k2] = __hadd2(a, b2);
        }
      }
      __syncthreads();

      // -------- GEMMs --------
      float acc1[12][4];  // [g*4+s]: gate g in {i,o,u}, col-subtile s
      float acc2[8][4];   // [s]: fl, [4+s]: fr
      #pragma unroll
      for (int i = 0; i < 12; i++){ acc1[i][0]=0.f; acc1[i][1]=0.f; acc1[i][2]=0.f; acc1[i][3]=0.f; }
      #pragma unroll
      for (int i = 0; i < 8; i++){ acc2[i][0]=0.f; acc2[i][1]=0.f; acc2[i][2]=0.f; acc2[i][3]=0.f; }

      #pragma unroll
      for (int k16 = 0; k16 < 8; k16++){
        const int kh = k16*16;
        const int arow = 16*wm + (lane & 15);
        const int acol = kh + (lane >> 4)*8;
        unsigned aT[4], aL[4], aR[4];
        ldsm4(saddr(&sHT[arow*PADH + acol]),        aT[0],aT[1],aT[2],aT[3]);
        ldsm4(saddr(&sLR[arow*PADH + acol]),        aL[0],aL[1],aL[2],aL[3]);
        ldsm4(saddr(&sLR[(64+arow)*PADH + acol]),   aR[0],aR[1],aR[2],aR[3]);

        const int brow_in = ((lane>>4)&1)*8 + (lane&7);
        const int bcol    = kh + ((lane>>3)&1)*8;
        #pragma unroll
        for (int g = 0; g < 3; g++){
          #pragma unroll
          for (int sp = 0; sp < 2; sp++){
            int R0 = 128*g + 32*wn + 16*sp;
            unsigned r0,r1,r2,r3;
            ldsm4(saddr(&sB[(R0 + brow_in)*PADH + bcol]), r0,r1,r2,r3);
            mma16816(acc1[g*4 + 2*sp + 0], aT, r0, r1);
            mma16816(acc1[g*4 + 2*sp + 1], aT, r2, r3);
          }
        }
        #pragma unroll
        for (int sp = 0; sp < 2; sp++){
          int R0 = 384 + 32*wn + 16*sp;
          unsigned r0,r1,r2,r3;
          ldsm4(saddr(&sB[(R0 + brow_in)*PADH + bcol]), r0,r1,r2,r3);
          mma16816(acc2[2*sp + 0], aL, r0, r1);
          mma16816(acc2[2*sp + 1], aL, r2, r3);
          mma16816(acc2[4 + 2*sp + 0], aR, r0, r1);
          mma16816(acc2[4 + 2*sp + 1], aR, r2, r3);
        }
      }

      // -------- epilogue --------
      const int cpair = (lane & 3)*2;
      #pragma unroll
      for (int half = 0; half < 2; half++){
        int rloc = (lane >> 2) + half*8;
        int nl = 16*wm + rloc;
        int n_g = node0 + nl;
        int sym = sSym[nl];
        int i0 = sIdx0[nl], i1 = sIdx1[nl];
        const float2* cl2p = (const float2*)(Csrc + i0*H_);
        const float2* cr2p = (const float2*)(Csrc + i1*H_);
        const float2* ai2  = (const float2*)(g_tai + sym*H_);
        const float2* ao2  = (const float2*)(g_tao + sym*H_);
        const float2* au2  = (const float2*)(g_tau + sym*H_);
        const float2* af2  = (const float2*)(g_taf + sym*H_);
        float2*  co = (float2*)(Cdst + n_g*H_);
        __half2* ho = (__half2*)(Hdst + n_g*H_);
        const int e = 2*half;
        #pragma unroll
        for (int s = 0; s < 4; s++){
          int c  = 32*wn + 8*s + cpair;
          int c2 = c >> 1;
          float2 ta = __ldg(ai2 + c2), to = __ldg(ao2 + c2);
          float2 tu = __ldg(au2 + c2), tf = __ldg(af2 + c2);
          float2 cl = __ldg(cl2p + c2), cr = __ldg(cr2p + c2);
          float pi0 = acc1[0*4+s][e]   + ta.x, pi1 = acc1[0*4+s][e+1] + ta.y;
          float po0 = acc1[1*4+s][e]   + to.x, po1 = acc1[1*4+s][e+1] + to.y;
          float pu0 = acc1[2*4+s][e]   + tu.x, pu1 = acc1[2*4+s][e+1] + tu.y;
          float fl0 = acc2[s][e]       + tf.x, fl1 = acc2[s][e+1]     + tf.y;
          float fr0 = acc2[4+s][e]     + tf.x, fr1 = acc2[4+s][e+1]   + tf.y;
          float cn0 = sigmf_(pi0)*tanhf_(pu0) + sigmf_(fl0)*cl.x + sigmf_(fr0)*cr.x;
          float cn1 = sigmf_(pi1)*tanhf_(pu1) + sigmf_(fl1)*cl.y + sigmf_(fr1)*cr.y;
          float h0 = sigmf_(po0)*tanhf_(cn0);
          float h1 = sigmf_(po1)*tanhf_(cn1);
          co[c2] = make_float2(cn0, cn1);
          ho[c2] = __floats2half2_rn(h0, h1);
          if (m == 1){
            ((float2*)(g_hroot + n_g*H_))[c2] = make_float2(h0, h1);
          }
        }
      }
      __syncthreads();   // smem reuse next tile
    }

    // grid-wide barrier between levels
    __syncthreads();
    if (tid == 0){
      __threadfence();
      atomicAdd(&g_bar, 1u);
      const unsigned target = (unsigned)(NCTAS*(lvl+1));
      while (atomicAdd(&g_bar, 0u) < target) __nanosleep(64);
      __threadfence();
    }
    __syncthreads();
    off += m; m >>= 1;
  }

  // final projection: out = hroot @ Wout^T + bout  (fp32)
  if (blockIdx.x == 0){
    for (int idx = tid; idx < B_*H_; idx += THREADS){
      int b = idx >> 7, o = idx & 127;
      float acc = bout[o];
      const float* w  = Wout + o*H_;
      const float* hr = g_hroot + b*H_;
      #pragma unroll 8
      for (int k = 0; k < H_; k++) acc += hr[k]*w[k];
      out[idx] = acc;
    }
  }
}

// ---------------- host orchestration ----------------
extern "C" void kernel_launch(void* const* d_in, const int* in_sizes, int n_in,
                              void* d_out, int out_size) {
  const int*   tokens  = (const int*)  d_in[0];
  const int*   symbols = (const int*)  d_in[1];
  const float* emb     = (const float*)d_in[2];
  const float* sym_emb = (const float*)d_in[3];
  const float* Wp   = (const float*)d_in[4];
  const float* bp   = (const float*)d_in[5];
  const float* Wi   = (const float*)d_in[6];
  const float* bi   = (const float*)d_in[7];
  const float* Ui   = (const float*)d_in[8];
  const float* Wf   = (const float*)d_in[9];
  const float* bf   = (const float*)d_in[10];
  const float* Uf   = (const float*)d_in[11];
  const float* Wo   = (const float*)d_in[12];
  const float* bo   = (const float*)d_in[13];
  const float* Uo   = (const float*)d_in[14];
  const float* Wu   = (const float*)d_in[15];
  const float* bu   = (const float*)d_in[16];
  const float* Uu   = (const float*)d_in[17];
  const float* Wout = (const float*)d_in[18];
  const float* bout = (const float*)d_in[19];

  const int smemBytes = (512 + 64 + 128)*PADH*(int)sizeof(__half) + 3*64*(int)sizeof(int);
  cudaFuncSetAttribute(tree_kernel, cudaFuncAttributeMaxDynamicSharedMemorySize, smemBytes);

  tables_kernel<<<V_ + S_, H_>>>(emb, sym_emb, Wp, bp, Wi, bi, Wf, bf, Wo, bo, Wu, bu);
  prepU_kernel<<<256, 256>>>(Ui, Uo, Uu, Uf);
  tree_kernel<<<NCTAS, THREADS, smemBytes>>>(tokens, symbols, Wout, bout, (float*)d_out);
}

// round 5
// speedup vs baseline: 1.8743x; 1.8743x over previous
#include <cuda_runtime.h>
#include <cuda_fp16.h>
#include <stdint.h>
#include <math.h>

#define B_ 64
#define N_ 4096
#define V_ 21
#define S_ 50
#define E_ 64
#define H_ 128
#define THREADS 512
#define NCTAS 148
#define PADH 136      // halves per padded smem row (272B): conflict-benign ldsm

// smem layout (bytes)
#define SMU_BYTES (512*PADH*2)          // 139264: U-concat rows 0-127 Ui,128-255 Uo,256-383 Uu,384-511 Uf
#define HTILE_BYTES (64*PADH*2)         // 17408
#define BUF_BYTES (2*HTILE_BYTES)       // HT + HR
#define SM_TOTAL (SMU_BYTES + 2*BUF_BYTES)   // 208896

// ---------------- static device scratch ----------------
__device__ float  g_tai[S_*H_], g_tao[S_*H_], g_tau[S_*H_], g_taf[S_*H_];
__device__ __half g_h016[V_*H_];
__device__ float  g_c0[V_*H_];
__device__ __half g_HA[B_*2048*H_];
__device__ __half g_HB[B_*1024*H_];
__device__ float  g_CA[B_*2048*H_];
__device__ float  g_CB[B_*1024*H_];
__device__ float  g_hroot[B_*H_];
__device__ unsigned g_bar;    // zero-init; reset by last CTA each launch
__device__ unsigned g_done;

__device__ __forceinline__ float tha(float x){
  float y; asm("tanh.approx.f32 %0, %1;" : "=f"(y) : "f"(x)); return y;
}
__device__ __forceinline__ float sga(float x){ return 0.5f*tha(0.5f*x) + 0.5f; }

__device__ __forceinline__ unsigned saddr(const void* p){
  return (unsigned)__cvta_generic_to_shared(p);
}
__device__ __forceinline__ void ldsm4(unsigned addr, unsigned &r0, unsigned &r1, unsigned &r2, unsigned &r3){
  asm volatile("ldmatrix.sync.aligned.m8n8.x4.shared.b16 {%0,%1,%2,%3}, [%4];"
    : "=r"(r0),"=r"(r1),"=r"(r2),"=r"(r3) : "r"(addr));
}
__device__ __forceinline__ void mma16816(float d[4], const unsigned a[4], unsigned b0, unsigned b1){
  asm volatile("mma.sync.aligned.m16n8k16.row.col.f32.f16.f16.f32 "
    "{%0,%1,%2,%3}, {%4,%5,%6,%7}, {%8,%9}, {%0,%1,%2,%3};"
    : "+f"(d[0]),"+f"(d[1]),"+f"(d[2]),"+f"(d[3])
    : "r"(a[0]),"r"(a[1]),"r"(a[2]),"r"(a[3]), "r"(b0),"r"(b1));
}
__device__ __forceinline__ uint32_t hadd2u(uint32_t a, uint32_t b){
  __half2 r = __hadd2(*reinterpret_cast<__half2*>(&a), *reinterpret_cast<__half2*>(&b));
  return *reinterpret_cast<uint32_t*>(&r);
}
__device__ __forceinline__ uint32_t hsub2u(uint32_t a, uint32_t b){
  __half2 r = __hsub2(*reinterpret_cast<__half2*>(&a), *reinterpret_cast<__half2*>(&b));
  return *reinterpret_cast<uint32_t*>(&r);
}

// L2-only loads/stores for the cross-CTA ping-pong buffers (avoid stale L1 across levels)
__device__ __forceinline__ uint4 ldcg4(const uint4* p){
  uint4 v;
  asm volatile("ld.global.cg.v4.u32 {%0,%1,%2,%3}, [%4];"
    : "=r"(v.x),"=r"(v.y),"=r"(v.z),"=r"(v.w) : "l"(p));
  return v;
}
__device__ __forceinline__ float2 ldcg2f(const float2* p){
  float2 v;
  asm volatile("ld.global.cg.v2.f32 {%0,%1}, [%2];" : "=f"(v.x),"=f"(v.y) : "l"(p));
  return v;
}
__device__ __forceinline__ void stcg2f(float2* p, float2 v){
  asm volatile("st.global.cg.v2.f32 [%0], {%1,%2};" :: "l"(p), "f"(v.x), "f"(v.y) : "memory");
}
__device__ __forceinline__ void stcgu(uint32_t* p, uint32_t v){
  asm volatile("st.global.cg.u32 [%0], %1;" :: "l"(p), "r"(v) : "memory");
}

// stage 64-node tile: gather h rows, write sHT (=hl+hr) and sHR (=hr)
__device__ __forceinline__ void stage_tile(char* bufbase, const __half* Hsrc,
    const int* tokens, int lvl, int node0, int logm, int m, int tid){
  const uint4* H4 = (const uint4*)Hsrc;
  char* sHT = bufbase;
  char* sHR = bufbase + HTILE_BYTES;
  #pragma unroll 2
  for (int idx = tid; idx < 64*16; idx += THREADS){
    int r = idx >> 4, q = idx & 15;
    int n_g = node0 + r;
    int i0, i1;
    if (lvl == 0){
      int b = n_g >> logm, j = n_g & (m-1);
      i0 = __ldg(&tokens[b*N_ + 2*j]);
      i1 = __ldg(&tokens[b*N_ + 2*j + 1]);
    } else { i0 = 2*n_g; i1 = 2*n_g + 1; }
    uint4 a  = ldcg4(&H4[i0*16 + q]);
    uint4 b4 = ldcg4(&H4[i1*16 + q]);
    uint4 s;
    s.x = hadd2u(a.x, b4.x); s.y = hadd2u(a.y, b4.y);
    s.z = hadd2u(a.z, b4.z); s.w = hadd2u(a.w, b4.w);
    int boff = r*(PADH*2) + q*16;
    *(uint4*)(sHT + boff) = s;
    *(uint4*)(sHR + boff) = b4;
  }
}

// ---------------- fused persistent kernel ----------------
extern __shared__ char smx[];
__global__ __launch_bounds__(THREADS, 1) void fused_kernel(
  const int* __restrict__ tokens, const int* __restrict__ symbols,
  const float* __restrict__ emb, const float* __restrict__ sym_emb,
  const float* __restrict__ Wp, const float* __restrict__ bp,
  const float* __restrict__ Wi, const float* __restrict__ bi,
  const float* __restrict__ Ui, const float* __restrict__ Wf,
  const float* __restrict__ bf, const float* __restrict__ Uf,
  const float* __restrict__ Wo, const float* __restrict__ bo,
  const float* __restrict__ Uo, const float* __restrict__ Wu,
  const float* __restrict__ bu, const float* __restrict__ Uu,
  const float* __restrict__ Wout, const float* __restrict__ bout,
  float* __restrict__ out)
{
  const int tid = threadIdx.x;
  const int lane = tid & 31, wid = tid >> 5;
  const int wm = wid >> 2, wn = wid & 3;
  __half* sU = (__half*)smx;

  // ---- phase 0: stage fp16 U-concat into smem (every CTA) ----
  for (int idx = tid; idx < 512*32; idx += THREADS){
    int r = idx >> 5, q = idx & 31;     // r = output col row of concat, q = float4 along k
    const float* src = (r < 128) ? Ui + r*H_
                      : (r < 256) ? Uo + (r-128)*H_
                      : (r < 384) ? Uu + (r-256)*H_
                      :             Uf + (r-384)*H_;
    float4 v = __ldg((const float4*)src + q);
    __half2 h0 = __floats2half2_rn(v.x, v.y);
    __half2 h1 = __floats2half2_rn(v.z, v.w);
    uint2 u;
    u.x = *reinterpret_cast<uint32_t*>(&h0);
    u.y = *reinterpret_cast<uint32_t*>(&h1);
    *(uint2*)(smx + (r*PADH + q*4)*2) = u;
  }

  // ---- phase 0b: tables (CTAs 0..V+S-1, threads 0..127) ----
  if (blockIdx.x < V_ + S_){
    float* se = (float*)(smx + SMU_BYTES);          // scratch in buffer region
    float* sx = se + E_;
    const int v_or_s = blockIdx.x;
    const int h = tid;
    if (tid < E_)
      se[tid] = (v_or_s < V_) ? emb[v_or_s*E_ + tid] : sym_emb[(v_or_s - V_)*E_ + tid];
    __syncthreads();
    if (tid < H_){
      float x = bp[h];
      #pragma unroll 8
      for (int e = 0; e < E_; e++) x += se[e]*Wp[h*E_ + e];
      sx[h] = x;
    }
    __syncthreads();
    if (tid < H_){
      if (v_or_s < V_){
        float ai_ = bi[h], ao_ = bo[h], au_ = bu[h];
        #pragma unroll 8
        for (int k = 0; k < H_; k++){
          float xv = sx[k];
          ai_ += xv*Wi[h*H_+k]; ao_ += xv*Wo[h*H_+k]; au_ += xv*Wu[h*H_+k];
        }
        float gi = 1.f/(1.f+expf(-ai_)), go = 1.f/(1.f+expf(-ao_)), gu = tanhf(au_);
        float c = gi*gu;
        g_c0[v_or_s*H_+h] = c;
        g_h016[v_or_s*H_+h] = __float2half(go*tanhf(c));
      } else {
        int s = v_or_s - V_;
        float ai_ = bi[h], ao_ = bo[h], au_ = bu[h], af_ = bf[h];
        #pragma unroll 8
        for (int k = 0; k < H_; k++){
          float xv = sx[k];
          ai_ += xv*Wi[h*H_+k]; ao_ += xv*Wo[h*H_+k];
          au_ += xv*Wu[h*H_+k]; af_ += xv*Wf[h*H_+k];
        }
        g_tai[s*H_+h] = ai_; g_tao[s*H_+h] = ao_;
        g_tau[s*H_+h] = au_; g_taf[s*H_+h] = af_;
      }
    }
  }

  // ---- grid barrier helper (inline) ----
  unsigned ep = 0;
  #define GRID_BAR() do { \
    ep++; \
    __syncthreads(); \
    if (tid == 0){ \
      __threadfence(); \
      atomicAdd(&g_bar, 1u); \
      const unsigned tgt = ep*NCTAS; \
      while (*(volatile unsigned*)&g_bar < tgt) __nanosleep(32); \
      __threadfence(); \
    } \
    __syncthreads(); \
  } while(0)

  GRID_BAR();   // tables + U smem ready

  int m = 2048, off = 0;
  for (int lvl = 0; lvl < 12; lvl++){
    const __half* Hsrc; const float* Csrc;
    __half* Hdst; float* Cdst;
    if (lvl == 0)     { Hsrc = g_h016; Csrc = g_c0; }
    else if (lvl & 1) { Hsrc = g_HA;   Csrc = g_CA; }
    else              { Hsrc = g_HB;   Csrc = g_CB; }
    if (lvl & 1) { Hdst = g_HB; Cdst = g_CB; } else { Hdst = g_HA; Cdst = g_CA; }

    const int tiles = (B_*m) >> 6;
    const int logm  = 31 - __clz(m);

    int t = blockIdx.x;
    int buf = 0;
    if (t < tiles)
      stage_tile(smx + SMU_BYTES + buf*BUF_BYTES, Hsrc, tokens, lvl, t << 6, logm, m, tid);
    __syncthreads();

    for (; t < tiles; t += NCTAS){
      const int node0 = t << 6;
      char* bb = smx + SMU_BYTES + buf*BUF_BYTES;
      __half* sHT = (__half*)bb;
      __half* sHR = (__half*)(bb + HTILE_BYTES);

      // -------- GEMMs --------
      float acc1[12][4];
      float acc2[8][4];
      #pragma unroll
      for (int i = 0; i < 12; i++){ acc1[i][0]=0.f; acc1[i][1]=0.f; acc1[i][2]=0.f; acc1[i][3]=0.f; }
      #pragma unroll
      for (int i = 0; i < 8; i++){ acc2[i][0]=0.f; acc2[i][1]=0.f; acc2[i][2]=0.f; acc2[i][3]=0.f; }

      #pragma unroll
      for (int k16 = 0; k16 < 8; k16++){
        const int kh = k16*16;
        const int arow = 16*wm + (lane & 15);
        const int acol = kh + (lane >> 4)*8;
        unsigned aT[4], aR[4], aL[4];
        ldsm4(saddr(&sHT[arow*PADH + acol]), aT[0],aT[1],aT[2],aT[3]);
        ldsm4(saddr(&sHR[arow*PADH + acol]), aR[0],aR[1],aR[2],aR[3]);
        #pragma unroll
        for (int i = 0; i < 4; i++) aL[i] = hsub2u(aT[i], aR[i]);   // hl = ht - hr

        const int brow_in = ((lane>>4)&1)*8 + (lane&7);
        const int bcol    = kh + ((lane>>3)&1)*8;
        #pragma unroll
        for (int g = 0; g < 3; g++){
          #pragma unroll
          for (int sp = 0; sp < 2; sp++){
            int R0 = 128*g + 32*wn + 16*sp;
            unsigned r0,r1,r2,r3;
            ldsm4(saddr(&sU[(R0 + brow_in)*PADH + bcol]), r0,r1,r2,r3);
            mma16816(acc1[g*4 + 2*sp + 0], aT, r0, r1);
            mma16816(acc1[g*4 + 2*sp + 1], aT, r2, r3);
          }
        }
        #pragma unroll
        for (int sp = 0; sp < 2; sp++){
          int R0 = 384 + 32*wn + 16*sp;
          unsigned r0,r1,r2,r3;
          ldsm4(saddr(&sU[(R0 + brow_in)*PADH + bcol]), r0,r1,r2,r3);
          mma16816(acc2[2*sp + 0], aL, r0, r1);
          mma16816(acc2[2*sp + 1], aL, r2, r3);
          mma16816(acc2[4 + 2*sp + 0], aR, r0, r1);
          mma16816(acc2[4 + 2*sp + 1], aR, r2, r3);
        }
      }

      // -------- prefetch next tile while epilogue runs --------
      {
        int tn = t + NCTAS;
        if (tn < tiles)
          stage_tile(smx + SMU_BYTES + (buf^1)*BUF_BYTES, Hsrc, tokens, lvl, tn << 6, logm, m, tid);
      }

      // -------- epilogue --------
      const int cpair = (lane & 3)*2;
      #pragma unroll
      for (int half = 0; half < 2; half++){
        int nl = 16*wm + (lane >> 2) + 8*half;
        int n_g = node0 + nl;
        int b = n_g >> logm, j = n_g & (m-1);
        int sym = __ldg(&symbols[b*(N_-1) + off + j]);
        int i0, i1;
        if (lvl == 0){ i0 = __ldg(&tokens[b*N_ + 2*j]); i1 = __ldg(&tokens[b*N_ + 2*j + 1]); }
        else         { i0 = 2*n_g; i1 = 2*n_g + 1; }
        const float2* cl2p = (const float2*)(Csrc + i0*H_);
        const float2* cr2p = (const float2*)(Csrc + i1*H_);
        const float2* ai2  = (const float2*)(g_tai + sym*H_);
        const float2* ao2  = (const float2*)(g_tao + sym*H_);
        const float2* au2  = (const float2*)(g_tau + sym*H_);
        const float2* af2  = (const float2*)(g_taf + sym*H_);
        float2*  co = (float2*)(Cdst + n_g*H_);
        uint32_t* ho = (uint32_t*)(Hdst + n_g*H_);
        const int e = 2*half;
        #pragma unroll
        for (int s = 0; s < 4; s++){
          int c2 = (32*wn + 8*s + cpair) >> 1;
          float2 ta = __ldg(ai2 + c2), to = __ldg(ao2 + c2);
          float2 tu = __ldg(au2 + c2), tf = __ldg(af2 + c2);
          float2 cl = ldcg2f(cl2p + c2), cr = ldcg2f(cr2p + c2);
          float pi0 = acc1[0*4+s][e]   + ta.x, pi1 = acc1[0*4+s][e+1] + ta.y;
          float po0 = acc1[1*4+s][e]   + to.x, po1 = acc1[1*4+s][e+1] + to.y;
          float pu0 = acc1[2*4+s][e]   + tu.x, pu1 = acc1[2*4+s][e+1] + tu.y;
          float fl0 = acc2[s][e]       + tf.x, fl1 = acc2[s][e+1]     + tf.y;
          float fr0 = acc2[4+s][e]     + tf.x, fr1 = acc2[4+s][e+1]   + tf.y;
          float cn0 = sga(pi0)*tha(pu0) + sga(fl0)*cl.x + sga(fr0)*cr.x;
          float cn1 = sga(pi1)*tha(pu1) + sga(fl1)*cl.y + sga(fr1)*cr.y;
          float h0 = sga(po0)*tha(cn0);
          float h1 = sga(po1)*tha(cn1);
          stcg2f(co + c2, make_float2(cn0, cn1));
          __half2 hh = __floats2half2_rn(h0, h1);
          stcgu(ho + c2, *reinterpret_cast<uint32_t*>(&hh));
          if (m == 1)
            ((float2*)(g_hroot + n_g*H_))[c2] = make_float2(h0, h1);
        }
      }
      __syncthreads();
      buf ^= 1;
    }

    GRID_BAR();
    off += m; m >>= 1;
  }

  // ---- final projection: out = hroot @ Wout^T + bout ----
  for (int idx = blockIdx.x*THREADS + tid; idx < B_*H_; idx += NCTAS*THREADS){
    int b = idx >> 7, o = idx & 127;
    float acc = bout[o];
    const float* w  = Wout + o*H_;
    const float* hr = g_hroot + b*H_;
    #pragma unroll 8
    for (int k = 0; k < H_; k++) acc += hr[k]*w[k];
    out[idx] = acc;
  }

  // ---- reset barrier counters for next graph replay (safe: all CTAs past all waits) ----
  __syncthreads();
  if (tid == 0){
    unsigned d = atomicAdd(&g_done, 1u) + 1u;
    if (d == NCTAS){
      atomicExch(&g_bar, 0u);
      atomicExch(&g_done, 0u);
    }
  }
}

// ---------------- host orchestration ----------------
extern "C" void kernel_launch(void* const* d_in, const int* in_sizes, int n_in,
                              void* d_out, int out_size) {
  const int*   tokens  = (const int*)  d_in[0];
  const int*   symbols = (const int*)  d_in[1];
  const float* emb     = (const float*)d_in[2];
  const float* sym_emb = (const float*)d_in[3];
  const float* Wp   = (const float*)d_in[4];
  const float* bp   = (const float*)d_in[5];
  const float* Wi   = (const float*)d_in[6];
  const float* bi   = (const float*)d_in[7];
  const float* Ui   = (const float*)d_in[8];
  const float* Wf   = (const float*)d_in[9];
  const float* bf   = (const float*)d_in[10];
  const float* Uf   = (const float*)d_in[11];
  const float* Wo   = (const float*)d_in[12];
  const float* bo   = (const float*)d_in[13];
  const float* Uo   = (const float*)d_in[14];
  const float* Wu   = (const float*)d_in[15];
  const float* bu   = (const float*)d_in[16];
  const float* Uu   = (const float*)d_in[17];
  const float* Wout = (const float*)d_in[18];
  const float* bout = (const float*)d_in[19];

  cudaFuncSetAttribute(fused_kernel, cudaFuncAttributeMaxDynamicSharedMemorySize, SM_TOTAL);
  fused_kernel<<<NCTAS, THREADS, SM_TOTAL>>>(
      tokens, symbols, emb, sym_emb, Wp, bp, Wi, bi, Ui, Wf, bf, Uf,
      Wo, bo, Uo, Wu, bu, Uu, Wout, bout, (float*)d_out);
}

// round 6
// speedup vs baseline: 2.1574x; 1.1510x over previous
#include <cuda_runtime.h>
#include <cuda_fp16.h>
#include <stdint.h>
#include <math.h>

#define B_ 64
#define N_ 4096
#define V_ 21
#define S_ 50
#define E_ 64
#define H_ 128
#define THREADS 512
#define NCTAS 148
#define PADH 136      // halves per padded smem row (272B)

// smem layout (bytes)
#define SMU_BYTES (512*PADH*2)          // 139264: U-concat
#define HTILE_BYTES (64*PADH*2)         // 17408
#define BUF_BYTES (2*HTILE_BYTES)       // 34816 (HT+HR)
#define SM_TOTAL (SMU_BYTES + 2*BUF_BYTES)   // 208896

// deep-phase layout inside the buffer region (offsets from SMU_BYTES)
#define DP_H    0        // 64 rows x 256B fp16
#define DP_C    16384    // 64 rows x 512B fp32
#define DP_A    49152    // HT 32x272 = 8704, HR 8704
#define DP_ROOT 66560    // 128 floats

// ---------------- static device scratch ----------------
__device__ float  g_tai[S_*H_], g_tao[S_*H_], g_tau[S_*H_], g_taf[S_*H_];
__device__ __half g_h016[V_*H_];
__device__ float  g_c0[V_*H_];
__device__ __half g_HA[B_*2048*H_];
__device__ __half g_HB[B_*1024*H_];
__device__ float  g_CA[B_*2048*H_];
__device__ float  g_CB[B_*1024*H_];
__device__ unsigned g_bar;
__device__ unsigned g_done;

__device__ __forceinline__ float tha(float x){
  float y; asm("tanh.approx.f32 %0, %1;" : "=f"(y) : "f"(x)); return y;
}
__device__ __forceinline__ float sga(float x){ return 0.5f*tha(0.5f*x) + 0.5f; }

__device__ __forceinline__ unsigned saddr(const void* p){
  return (unsigned)__cvta_generic_to_shared(p);
}
__device__ __forceinline__ void ldsm4(unsigned addr, unsigned &r0, unsigned &r1, unsigned &r2, unsigned &r3){
  asm volatile("ldmatrix.sync.aligned.m8n8.x4.shared.b16 {%0,%1,%2,%3}, [%4];"
    : "=r"(r0),"=r"(r1),"=r"(r2),"=r"(r3) : "r"(addr));
}
__device__ __forceinline__ void mma16816(float d[4], const unsigned a[4], unsigned b0, unsigned b1){
  asm volatile("mma.sync.aligned.m16n8k16.row.col.f32.f16.f16.f32 "
    "{%0,%1,%2,%3}, {%4,%5,%6,%7}, {%8,%9}, {%0,%1,%2,%3};"
    : "+f"(d[0]),"+f"(d[1]),"+f"(d[2]),"+f"(d[3])
    : "r"(a[0]),"r"(a[1]),"r"(a[2]),"r"(a[3]), "r"(b0),"r"(b1));
}
__device__ __forceinline__ uint32_t hadd2u(uint32_t a, uint32_t b){
  __half2 r = __hadd2(*reinterpret_cast<__half2*>(&a), *reinterpret_cast<__half2*>(&b));
  return *reinterpret_cast<uint32_t*>(&r);
}
__device__ __forceinline__ uint32_t hsub2u(uint32_t a, uint32_t b){
  __half2 r = __hsub2(*reinterpret_cast<__half2*>(&a), *reinterpret_cast<__half2*>(&b));
  return *reinterpret_cast<uint32_t*>(&r);
}
__device__ __forceinline__ uint4 ldcg4(const uint4* p){
  uint4 v;
  asm volatile("ld.global.cg.v4.u32 {%0,%1,%2,%3}, [%4];"
    : "=r"(v.x),"=r"(v.y),"=r"(v.z),"=r"(v.w) : "l"(p));
  return v;
}
__device__ __forceinline__ float2 ldcg2f(const float2* p){
  float2 v;
  asm volatile("ld.global.cg.v2.f32 {%0,%1}, [%2];" : "=f"(v.x),"=f"(v.y) : "l"(p));
  return v;
}
__device__ __forceinline__ void stcg2f(float2* p, float2 v){
  asm volatile("st.global.cg.v2.f32 [%0], {%1,%2};" :: "l"(p), "f"(v.x), "f"(v.y) : "memory");
}
__device__ __forceinline__ void stcgu(uint32_t* p, uint32_t v){
  asm volatile("st.global.cg.u32 [%0], %1;" :: "l"(p), "r"(v) : "memory");
}

// ---------------- shared GEMM tile: 64(or 32) rows x 128 cols, 5 gate-products ----------------
__device__ __forceinline__ void gemm_tile(const __half* sU, const __half* sHT, const __half* sHR,
                                          int lane, int wm, int wn,
                                          float acc1[12][4], float acc2[8][4]){
  #pragma unroll
  for (int i = 0; i < 12; i++){ acc1[i][0]=0.f; acc1[i][1]=0.f; acc1[i][2]=0.f; acc1[i][3]=0.f; }
  #pragma unroll
  for (int i = 0; i < 8; i++){ acc2[i][0]=0.f; acc2[i][1]=0.f; acc2[i][2]=0.f; acc2[i][3]=0.f; }
  #pragma unroll
  for (int k16 = 0; k16 < 8; k16++){
    const int kh = k16*16;
    const int arow = 16*wm + (lane & 15);
    const int acol = kh + (lane >> 4)*8;
    unsigned aT[4], aR[4], aL[4];
    ldsm4(saddr(&sHT[arow*PADH + acol]), aT[0],aT[1],aT[2],aT[3]);
    ldsm4(saddr(&sHR[arow*PADH + acol]), aR[0],aR[1],aR[2],aR[3]);
    #pragma unroll
    for (int i = 0; i < 4; i++) aL[i] = hsub2u(aT[i], aR[i]);   // hl = ht - hr

    const int brow_in = ((lane>>4)&1)*8 + (lane&7);
    const int bcol    = kh + ((lane>>3)&1)*8;
    #pragma unroll
    for (int g = 0; g < 3; g++){
      #pragma unroll
      for (int sp = 0; sp < 2; sp++){
        int R0 = 128*g + 32*wn + 16*sp;
        unsigned r0,r1,r2,r3;
        ldsm4(saddr(&sU[(R0 + brow_in)*PADH + bcol]), r0,r1,r2,r3);
        mma16816(acc1[g*4 + 2*sp + 0], aT, r0, r1);
        mma16816(acc1[g*4 + 2*sp + 1], aT, r2, r3);
      }
    }
    #pragma unroll
    for (int sp = 0; sp < 2; sp++){
      int R0 = 384 + 32*wn + 16*sp;
      unsigned r0,r1,r2,r3;
      ldsm4(saddr(&sU[(R0 + brow_in)*PADH + bcol]), r0,r1,r2,r3);
      mma16816(acc2[2*sp + 0], aL, r0, r1);
      mma16816(acc2[2*sp + 1], aL, r2, r3);
      mma16816(acc2[4 + 2*sp + 0], aR, r0, r1);
      mma16816(acc2[4 + 2*sp + 1], aR, r2, r3);
    }
  }
}

// stage 64-node big-level tile from gmem
__device__ __forceinline__ void stage_tile(char* bufbase, const __half* Hsrc,
    const int* tokens, int lvl, int node0, int logm, int m, int tid){
  const uint4* H4 = (const uint4*)Hsrc;
  char* sHT = bufbase;
  char* sHR = bufbase + HTILE_BYTES;
  #pragma unroll 2
  for (int idx = tid; idx < 64*16; idx += THREADS){
    int r = idx >> 4, q = idx & 15;
    int n_g = node0 + r;
    int i0, i1;
    if (lvl == 0){
      int b = n_g >> logm, j = n_g & (m-1);
      i0 = __ldg(&tokens[b*N_ + 2*j]);
      i1 = __ldg(&tokens[b*N_ + 2*j + 1]);
    } else { i0 = 2*n_g; i1 = 2*n_g + 1; }
    uint4 a  = ldcg4(&H4[i0*16 + q]);
    uint4 b4 = ldcg4(&H4[i1*16 + q]);
    uint4 s;
    s.x = hadd2u(a.x, b4.x); s.y = hadd2u(a.y, b4.y);
    s.z = hadd2u(a.z, b4.z); s.w = hadd2u(a.w, b4.w);
    int boff = r*(PADH*2) + q*16;
    *(uint4*)(sHT + boff) = s;
    *(uint4*)(sHR + boff) = b4;
  }
}

// ---------------- fused persistent kernel ----------------
extern __shared__ char smx[];
__global__ __launch_bounds__(THREADS, 1) void fused_kernel(
  const int* __restrict__ tokens, const int* __restrict__ symbols,
  const float* __restrict__ emb, const float* __restrict__ sym_emb,
  const float* __restrict__ Wp, const float* __restrict__ bp,
  const float* __restrict__ Wi, const float* __restrict__ bi,
  const float* __restrict__ Ui, const float* __restrict__ Wf,
  const float* __restrict__ bf, const float* __restrict__ Uf,
  const float* __restrict__ Wo, const float* __restrict__ bo,
  const float* __restrict__ Uo, const float* __restrict__ Wu,
  const float* __restrict__ bu, const float* __restrict__ Uu,
  const float* __restrict__ Wout, const float* __restrict__ bout,
  float* __restrict__ out)
{
  const int tid = threadIdx.x;
  const int lane = tid & 31, wid = tid >> 5;
  const int wm = wid >> 2, wn = wid & 3;
  __half* sU = (__half*)smx;

  // ---- phase 0: stage fp16 U-concat into smem ----
  for (int idx = tid; idx < 512*32; idx += THREADS){
    int r = idx >> 5, q = idx & 31;
    const float* src = (r < 128) ? Ui + r*H_
                      : (r < 256) ? Uo + (r-128)*H_
                      : (r < 384) ? Uu + (r-256)*H_
                      :             Uf + (r-384)*H_;
    float4 v = __ldg((const float4*)src + q);
    __half2 h0 = __floats2half2_rn(v.x, v.y);
    __half2 h1 = __floats2half2_rn(v.z, v.w);
    uint2 u;
    u.x = *reinterpret_cast<uint32_t*>(&h0);
    u.y = *reinterpret_cast<uint32_t*>(&h1);
    *(uint2*)(smx + (r*PADH + q*4)*2) = u;
  }

  // ---- phase 0b: tables ----
  if (blockIdx.x < V_ + S_){
    float* se = (float*)(smx + SMU_BYTES);
    float* sx = se + E_;
    const int v_or_s = blockIdx.x;
    const int h = tid;
    if (tid < E_)
      se[tid] = (v_or_s < V_) ? emb[v_or_s*E_ + tid] : sym_emb[(v_or_s - V_)*E_ + tid];
    __syncthreads();
    if (tid < H_){
      float x = bp[h];
      #pragma unroll 8
      for (int e = 0; e < E_; e++) x += se[e]*Wp[h*E_ + e];
      sx[h] = x;
    }
    __syncthreads();
    if (tid < H_){
      if (v_or_s < V_){
        float ai_ = bi[h], ao_ = bo[h], au_ = bu[h];
        #pragma unroll 8
        for (int k = 0; k < H_; k++){
          float xv = sx[k];
          ai_ += xv*Wi[h*H_+k]; ao_ += xv*Wo[h*H_+k]; au_ += xv*Wu[h*H_+k];
        }
        float gi = 1.f/(1.f+expf(-ai_)), go = 1.f/(1.f+expf(-ao_)), gu = tanhf(au_);
        float c = gi*gu;
        g_c0[v_or_s*H_+h] = c;
        g_h016[v_or_s*H_+h] = __float2half(go*tanhf(c));
      } else {
        int s = v_or_s - V_;
        float ai_ = bi[h], ao_ = bo[h], au_ = bu[h], af_ = bf[h];
        #pragma unroll 8
        for (int k = 0; k < H_; k++){
          float xv = sx[k];
          ai_ += xv*Wi[h*H_+k]; ao_ += xv*Wo[h*H_+k];
          au_ += xv*Wu[h*H_+k]; af_ += xv*Wf[h*H_+k];
        }
        g_tai[s*H_+h] = ai_; g_tao[s*H_+h] = ao_;
        g_tau[s*H_+h] = au_; g_taf[s*H_+h] = af_;
      }
    }
  }

  unsigned ep = 0;
  #define GRID_BAR() do { \
    ep++; \
    __syncthreads(); \
    if (tid == 0){ \
      __threadfence(); \
      atomicAdd(&g_bar, 1u); \
      const unsigned tgt = ep*NCTAS; \
      while (*(volatile unsigned*)&g_bar < tgt) __nanosleep(32); \
      __threadfence(); \
    } \
    __syncthreads(); \
  } while(0)

  GRID_BAR();   // tables + U ready

  // ---- big levels: lvl 0..5 (m = 2048..64) ----
  int m = 2048, off = 0;
  for (int lvl = 0; lvl < 6; lvl++){
    const __half* Hsrc; const float* Csrc;
    __half* Hdst; float* Cdst;
    if (lvl == 0)     { Hsrc = g_h016; Csrc = g_c0; }
    else if (lvl & 1) { Hsrc = g_HA;   Csrc = g_CA; }
    else              { Hsrc = g_HB;   Csrc = g_CB; }
    if (lvl & 1) { Hdst = g_HB; Cdst = g_CB; } else { Hdst = g_HA; Cdst = g_CA; }

    const int tiles = (B_*m) >> 6;
    const int logm  = 31 - __clz(m);

    int t = blockIdx.x;
    int buf = 0;
    if (t < tiles)
      stage_tile(smx + SMU_BYTES + buf*BUF_BYTES, Hsrc, tokens, lvl, t << 6, logm, m, tid);
    __syncthreads();

    for (; t < tiles; t += NCTAS){
      const int node0 = t << 6;
      char* bb = smx + SMU_BYTES + buf*BUF_BYTES;

      float acc1[12][4], acc2[8][4];
      gemm_tile(sU, (const __half*)bb, (const __half*)(bb + HTILE_BYTES), lane, wm, wn, acc1, acc2);

      // prefetch next tile while epilogue runs
      {
        int tn = t + NCTAS;
        if (tn < tiles)
          stage_tile(smx + SMU_BYTES + (buf^1)*BUF_BYTES, Hsrc, tokens, lvl, tn << 6, logm, m, tid);
      }

      // epilogue
      #pragma unroll
      for (int half = 0; half < 2; half++){
        int nl = 16*wm + (lane >> 2) + 8*half;
        int n_g = node0 + nl;
        int b = n_g >> logm, j = n_g & (m-1);
        int sym = __ldg(&symbols[b*(N_-1) + off + j]);
        int i0, i1;
        if (lvl == 0){ i0 = __ldg(&tokens[b*N_ + 2*j]); i1 = __ldg(&tokens[b*N_ + 2*j + 1]); }
        else         { i0 = 2*n_g; i1 = 2*n_g + 1; }
        const float2* cl2p = (const float2*)(Csrc + i0*H_);
        const float2* cr2p = (const float2*)(Csrc + i1*H_);
        const float2* ai2  = (const float2*)(g_tai + sym*H_);
        const float2* ao2  = (const float2*)(g_tao + sym*H_);
        const float2* au2  = (const float2*)(g_tau + sym*H_);
        const float2* af2  = (const float2*)(g_taf + sym*H_);
        float2*  co = (float2*)(Cdst + n_g*H_);
        uint32_t* ho = (uint32_t*)(Hdst + n_g*H_);
        const int e = 2*half;
        // batched loads (expose MLP)
        float2 cl[4], cr[4], tf[4];
        #pragma unroll
        for (int s = 0; s < 4; s++){
          int c2 = 16*wn + 4*s + (lane & 3);
          cl[s] = ldcg2f(cl2p + c2);
          cr[s] = ldcg2f(cr2p + c2);
          tf[s] = __ldg(af2 + c2);
        }
        #pragma unroll
        for (int s = 0; s < 4; s++){
          int c2 = 16*wn + 4*s + (lane & 3);
          float2 ta = __ldg(ai2 + c2), tu = __ldg(au2 + c2), to = __ldg(ao2 + c2);
          float pi0 = acc1[0*4+s][e]   + ta.x, pi1 = acc1[0*4+s][e+1] + ta.y;
          float pu0 = acc1[2*4+s][e]   + tu.x, pu1 = acc1[2*4+s][e+1] + tu.y;
          float fl0 = acc2[s][e]       + tf[s].x, fl1 = acc2[s][e+1]   + tf[s].y;
          float fr0 = acc2[4+s][e]     + tf[s].x, fr1 = acc2[4+s][e+1] + tf[s].y;
          float cn0 = sga(pi0)*tha(pu0) + sga(fl0)*cl[s].x + sga(fr0)*cr[s].x;
          float cn1 = sga(pi1)*tha(pu1) + sga(fl1)*cl[s].y + sga(fr1)*cr[s].y;
          float po0 = acc1[1*4+s][e]   + to.x, po1 = acc1[1*4+s][e+1] + to.y;
          float h0 = sga(po0)*tha(cn0);
          float h1 = sga(po1)*tha(cn1);
          stcg2f(co + c2, make_float2(cn0, cn1));
          __half2 hh = __floats2half2_rn(h0, h1);
          stcgu(ho + c2, *reinterpret_cast<uint32_t*>(&hh));
        }
      }
      __syncthreads();
      buf ^= 1;
    }

    off += m; m >>= 1;
    if (lvl < 5) GRID_BAR();
    // no barrier after lvl5: each CTA b < 64 produced exactly the rows it consumes next
  }

  // ---- deep phase: per-batch CTA, m = 32..1, all in smem ----
  if (blockIdx.x < B_){
    const int b = blockIdx.x;
    char* dpH = smx + SMU_BYTES + DP_H;
    char* dpC = smx + SMU_BYTES + DP_C;
    char* dpHT = smx + SMU_BYTES + DP_A;
    char* dpHR = dpHT + 8704;
    float* sRoot = (float*)(smx + SMU_BYTES + DP_ROOT);

    // pull this batch's 64 children (lvl5 output: g_HB/g_CB rows b*64..+63)
    {
      const uint4* HS = (const uint4*)g_HB;
      for (int idx = tid; idx < 64*16; idx += THREADS){
        int r = idx >> 4, q = idx & 15;
        *(uint4*)(dpH + r*256 + q*16) = ldcg4(&HS[(b*64 + r)*16 + q]);
      }
      const uint4* CS = (const uint4*)g_CB;
      for (int idx = tid; idx < 64*32; idx += THREADS){
        int r = idx >> 5, q = idx & 31;
        *(uint4*)(dpC + r*512 + q*16) = ldcg4(&CS[(b*64 + r)*32 + q]);
      }
    }
    __syncthreads();

    int offd = 4032;
    for (int dm = 32; dm >= 1; dm >>= 1){
      // stage A from smem children
      for (int idx = tid; idx < dm*16; idx += THREADS){
        int r = idx >> 4, q = idx & 15;
        uint4 a  = *(const uint4*)(dpH + (2*r)*256 + q*16);
        uint4 b4 = *(const uint4*)(dpH + (2*r+1)*256 + q*16);
        uint4 s;
        s.x = hadd2u(a.x, b4.x); s.y = hadd2u(a.y, b4.y);
        s.z = hadd2u(a.z, b4.z); s.w = hadd2u(a.w, b4.w);
        int boff = r*(PADH*2) + q*16;
        *(uint4*)(dpHT + boff) = s;
        *(uint4*)(dpHR + boff) = b4;
      }
      __syncthreads();

      const int nrb = (dm + 15) >> 4;
      const bool part = (wm < nrb);
      float acc1[12][4], acc2[8][4];
      if (part)
        gemm_tile(sU, (const __half*)dpHT, (const __half*)dpHR, lane, wm, wn, acc1, acc2);

      // phase A: read children c from smem into regs (before overwrite)
      float2 cpl[2][4], cpr[2][4];
      if (part){
        #pragma unroll
        for (int half = 0; half < 2; half++){
          int nl = 16*wm + (lane >> 2) + 8*half;
          if (nl < dm){
            #pragma unroll
            for (int s = 0; s < 4; s++){
              int c2 = 16*wn + 4*s + (lane & 3);
              cpl[half][s] = ((const float2*)(dpC + (2*nl)*512))[c2];
              cpr[half][s] = ((const float2*)(dpC + (2*nl+1)*512))[c2];
            }
          }
        }
      }
      __syncthreads();

      // phase B: compute + write parents
      if (part){
        #pragma unroll
        for (int half = 0; half < 2; half++){
          int nl = 16*wm + (lane >> 2) + 8*half;
          if (nl >= dm) continue;
          int sym = __ldg(&symbols[b*(N_-1) + offd + nl]);
          const float2* ai2 = (const float2*)(g_tai + sym*H_);
          const float2* ao2 = (const float2*)(g_tao + sym*H_);
          const float2* au2 = (const float2*)(g_tau + sym*H_);
          const float2* af2 = (const float2*)(g_taf + sym*H_);
          float2* co = (float2*)(dpC + nl*512);
          uint32_t* ho = (uint32_t*)(dpH + nl*256);
          const int e = 2*half;
          #pragma unroll
          for (int s = 0; s < 4; s++){
            int c2 = 16*wn + 4*s + (lane & 3);
            float2 ta = __ldg(ai2 + c2), tu = __ldg(au2 + c2);
            float2 tf = __ldg(af2 + c2), to = __ldg(ao2 + c2);
            float pi0 = acc1[0*4+s][e]   + ta.x, pi1 = acc1[0*4+s][e+1] + ta.y;
            float pu0 = acc1[2*4+s][e]   + tu.x, pu1 = acc1[2*4+s][e+1] + tu.y;
            float fl0 = acc2[s][e]       + tf.x, fl1 = acc2[s][e+1]     + tf.y;
            float fr0 = acc2[4+s][e]     + tf.x, fr1 = acc2[4+s][e+1]   + tf.y;
            float cn0 = sga(pi0)*tha(pu0) + sga(fl0)*cpl[half][s].x + sga(fr0)*cpr[half][s].x;
            float cn1 = sga(pi1)*tha(pu1) + sga(fl1)*cpl[half][s].y + sga(fr1)*cpr[half][s].y;
            float po0 = acc1[1*4+s][e]   + to.x, po1 = acc1[1*4+s][e+1] + to.y;
            float h0 = sga(po0)*tha(cn0);
            float h1 = sga(po1)*tha(cn1);
            co[c2] = make_float2(cn0, cn1);
            __half2 hh = __floats2half2_rn(h0, h1);
            ho[c2] = *reinterpret_cast<uint32_t*>(&hh);
            if (dm == 1)
              ((float2*)sRoot)[c2] = make_float2(h0, h1);
          }
        }
      }
      __syncthreads();
      offd += dm;
    }

    // projection for this batch: out[b, :] = sRoot @ Wout^T + bout
    if (tid < H_){
      const int o = tid;
      float acc = bout[o];
      const float* w = Wout + o*H_;
      #pragma unroll 8
      for (int k = 0; k < H_; k++) acc += sRoot[k]*w[k];
      out[b*H_ + o] = acc;
    }
  }

  // ---- reset barrier counters for next graph replay ----
  __syncthreads();
  if (tid == 0){
    unsigned d = atomicAdd(&g_done, 1u) + 1u;
    if (d == NCTAS){
      atomicExch(&g_bar, 0u);
      atomicExch(&g_done, 0u);
    }
  }
}

// ---------------- host orchestration ----------------
extern "C" void kernel_launch(void* const* d_in, const int* in_sizes, int n_in,
                              void* d_out, int out_size) {
  const int*   tokens  = (const int*)  d_in[0];
  const int*   symbols = (const int*)  d_in[1];
  const float* emb     = (const float*)d_in[2];
  const float* sym_emb = (const float*)d_in[3];
  const float* Wp   = (const float*)d_in[4];
  const float* bp   = (const float*)d_in[5];
  const float* Wi   = (const float*)d_in[6];
  const float* bi   = (const float*)d_in[7];
  const float* Ui   = (const float*)d_in[8];
  const float* Wf   = (const float*)d_in[9];
  const float* bf   = (const float*)d_in[10];
  const float* Uf   = (const float*)d_in[11];
  const float* Wo   = (const float*)d_in[12];
  const float* bo   = (const float*)d_in[13];
  const float* Uo   = (const float*)d_in[14];
  const float* Wu   = (const float*)d_in[15];
  const float* bu   = (const float*)d_in[16];
  const float* Uu   = (const float*)d_in[17];
  const float* Wout = (const float*)d_in[18];
  const float* bout = (const float*)d_in[19];

  cudaFuncSetAttribute(fused_kernel, cudaFuncAttributeMaxDynamicSharedMemorySize, SM_TOTAL);
  fused_kernel<<<NCTAS, THREADS, SM_TOTAL>>>(
      tokens, symbols, emb, sym_emb, Wp, bp, Wi, bi, Ui, Wf, bf, Uf,
      Wo, bo, Uo, Wu, bu, Uu, Wout, bout, (float*)d_out);
}